// round 15
// baseline (speedup 1.0000x reference)
#include <cuda_runtime.h>
#include <math.h>
#include <stdint.h>

#define B_  4
#define T_  32
#define C_  128
#define HW_ 1024
#define N_  4096
#define GD_ 64
#define M_  (T_*N_)      // 131072 rows, r = t*N_ + n
#define F_  512
#define KNP 136          // k-major pad (weights, O tile, qkv activations)
#define UP_ 272          // interleaved-B row stride (=16 mod 32: LDS.64 conflict-free)

// ---------------- scratch (device globals; no allocation) ----------------
static __device__ float g_mu[M_];
static __device__ float g_rs[M_];
static __device__ float g_q [(size_t)M_*C_];
static __device__ float g_k [(size_t)M_*C_];
static __device__ float g_v [(size_t)M_*C_];
static __device__ float g_at[(size_t)M_*C_];

// ---------------- helpers -------------------------------------------------
#define CP16(dst, src) asm volatile("cp.async.cg.shared.global [%0], [%1], 16;" \
                                    :: "r"(dst), "l"(src) : "memory")
#define CPCOMMIT()    asm volatile("cp.async.commit_group;" ::: "memory")
#define CPWAIT(n)     asm volatile("cp.async.wait_group %0;" :: "n"(n) : "memory")

#define FMA2(d, a, b)  asm("fma.rn.f32x2 %0, %1, %2, %0;" : "+l"(d) : "l"(a), "l"(b))
#define PACK2(d, lo, hi) asm("mov.b64 %0, {%1,%2};" : "=l"(d) : "f"(lo), "f"(hi))
#define UNPACK2(lo, hi, s) asm("mov.b64 {%0,%1}, %2;" : "=f"(lo), "=f"(hi) : "l"(s))

__device__ __forceinline__ float rna(float f){
    float r; asm("cvt.rna.tf32.f32 %0, %1;" : "=f"(r) : "f"(f)); return r;
}
__device__ __forceinline__ void mma8(float* d, const uint32_t* a,
                                     uint32_t b0, uint32_t b1){
    asm volatile(
        "mma.sync.aligned.m16n8k8.row.col.f32.tf32.tf32.f32 "
        "{%0,%1,%2,%3}, {%4,%5,%6,%7}, {%8,%9}, {%0,%1,%2,%3};"
        : "+f"(d[0]), "+f"(d[1]), "+f"(d[2]), "+f"(d[3])
        : "r"(a[0]), "r"(a[1]), "r"(a[2]), "r"(a[3]), "r"(b0), "r"(b1));
}
// 16B cp.async fill into [k][n] pad-KNP layout (512 threads), 128 n-cols.
__device__ __forceinline__ void fill_w16(uint32_t sbase,
                                         const float* __restrict__ W, size_t ldw,
                                         int kbeg, int kcnt, int col0, int tid)
{
    const int k0 = tid >> 5, n16 = (tid & 31) * 4;
    for (int p = 0; p < kcnt/16; p++){
        int k = k0 + 16*p;
        CP16(sbase + (uint32_t)(k*KNP + n16)*4u,
             W + (size_t)(kbeg + k)*ldw + col0 + n16);
    }
}
// MMA (qkv): A = weights [k][m] pad KNP, B = activations [k][n] pad KNP.
__device__ __forceinline__ void mma_blkW(
    float acc[][4], const float* __restrict__ sW,
    const float* __restrict__ sB,
    int ks0, int ks1, int kloc0, int m0, int n0, int gid, int tig)
{
    #pragma unroll 2
    for (int ks = ks0; ks < ks1; ks++){
        const int kA = (ks - kloc0)*8;
        const int kB = ks*8;
        uint32_t a[4];
        a[0] = __float_as_uint(sW[(kA+tig  )*KNP + m0 + gid    ]);
        a[1] = __float_as_uint(sW[(kA+tig  )*KNP + m0 + gid + 8]);
        a[2] = __float_as_uint(sW[(kA+tig+4)*KNP + m0 + gid    ]);
        a[3] = __float_as_uint(sW[(kA+tig+4)*KNP + m0 + gid + 8]);
        #pragma unroll
        for (int j = 0; j < 8; j++){
            const int nb = n0 + j*8 + gid;
            uint32_t b0 = __float_as_uint(sB[(kB+tig  )*KNP + nb]);
            uint32_t b1 = __float_as_uint(sB[(kB+tig+4)*KNP + nb]);
            mma8(acc[j], a, b0, b1);
        }
    }
}
// MMA (ffn): A = weights [k][m] pad KNP, B = interleaved [ks*4+tig][n*2+bit]
// pad UP_: fragment pair (k+tig, k+tig+4) = one LDS.64.
__device__ __forceinline__ void mma_blkI(
    float acc[][4], const float* __restrict__ sW,
    const float* __restrict__ sB,
    int ks0, int ks1, int kloc0, int m0, int n0, int gid, int tig)
{
    #pragma unroll 2
    for (int ks = ks0; ks < ks1; ks++){
        const int kA = (ks - kloc0)*8;
        uint32_t a[4];
        a[0] = __float_as_uint(sW[(kA+tig  )*KNP + m0 + gid    ]);
        a[1] = __float_as_uint(sW[(kA+tig  )*KNP + m0 + gid + 8]);
        a[2] = __float_as_uint(sW[(kA+tig+4)*KNP + m0 + gid    ]);
        a[3] = __float_as_uint(sW[(kA+tig+4)*KNP + m0 + gid + 8]);
        const float* bro = &sB[(ks*4 + tig)*UP_];
        #pragma unroll
        for (int j = 0; j < 8; j++){
            const int nb = n0 + j*8 + gid;
            float2 bb = *(const float2*)&bro[nb*2];
            mma8(acc[j], a, __float_as_uint(bb.x), __float_as_uint(bb.y));
        }
    }
}

// ---------------- kernel 1: merged QKV GEMM + ln1 stats (unchanged) ------
__global__ __launch_bounds__(512) void k_qkv_tc(
    const float* __restrict__ x, const float* __restrict__ gdn,
    const float* __restrict__ Wq, const float* __restrict__ bq,
    const float* __restrict__ Wk, const float* __restrict__ bk,
    const float* __restrict__ Wv, const float* __restrict__ bv)
{
    extern __shared__ float sm[];
    float* sX  = sm;
    float* sWa = sm + 26112;
    float* sWb = sm + 39168;
    const uint32_t sXu  = (uint32_t)__cvta_generic_to_shared(sX);
    const uint32_t sWau = (uint32_t)__cvta_generic_to_shared(sWa);
    const uint32_t sWbu = (uint32_t)__cvta_generic_to_shared(sWb);

    const int tid = threadIdx.x;
    const int lane = tid & 31, wid = tid >> 5;
    const int wm = wid >> 1, wn = wid & 1;
    const int gid = lane >> 2, tig = lane & 3;
    const int m0 = wm*16, n0 = wn*64;

    const int r0 = blockIdx.x * 128;
    const int t  = r0 / N_,  nn0 = r0 % N_;
    const int b  = nn0 / HW_, hw0 = nn0 % HW_;
    const float* xbt = x   + (size_t)(b*T_ + t) * C_ * HW_;
    const float* gbt = gdn + (size_t)(b*T_ + t) * GD_;

    {
        const int hw4 = (tid & 31)*4, c0 = tid >> 5;
        for (int p = 0; p < 8; p++){
            int c = c0 + 16*p;
            CP16(sXu + (uint32_t)(c*KNP + hw4)*4u,
                 xbt + (size_t)c*HW_ + hw0 + hw4);
        }
    }
    for (int p = 0; p < 4; p++){
        int i = tid + 512*p;
        int grow = i >> 5, col4 = (i & 31)*4;
        float gv = gbt[grow];
        float4 f4 = make_float4(gv, gv, gv, gv);
        *(float4*)&sX[(128+grow)*KNP + col4] = f4;
    }
    CPCOMMIT();                                             // G0
    fill_w16(sWau, Wq, C_, 0,  96, 0, tid); CPCOMMIT();     // G1
    fill_w16(sWbu, Wq, C_, 96, 96, 0, tid); CPCOMMIT();     // G2
    CPWAIT(1); __syncthreads();   // <=1 pending => G0 AND G1 done

    if (tid < 128){
        float s = 0.f, s2 = 0.f;
        for (int c = 0; c < 128; c++){ float v = sX[c*KNP + tid]; s += v; s2 += v*v; }
        float mu = s * (1.0f/C_);
        g_mu[r0+tid] = mu;
        g_rs[r0+tid] = rsqrtf(s2 * (1.0f/C_) - mu*mu + 1e-5f);
    }

    float acc[8][4];
    #define ZACC() { _Pragma("unroll") for(int j2=0;j2<8;j2++) \
                     _Pragma("unroll") for(int q2=0;q2<4;q2++) acc[j2][q2]=0.f; }
    #define EPI(OUTP, BS, Y) { \
        const int mcol = m0 + gid; \
        const float bs0 = BS[mcol], bs8 = BS[mcol+8]; \
        _Pragma("unroll") for (int j = 0; j < 8; j++){ \
            const int nhw = n0 + j*8 + 2*tig; \
            float v0 = acc[j][0]+bs0, v1 = acc[j][1]+bs0; \
            float v2 = acc[j][2]+bs8, v3 = acc[j][3]+bs8; \
            if (Y < 2){ \
                v0 = v0>0.f ? v0+1.f : expf(v0); v1 = v1>0.f ? v1+1.f : expf(v1); \
                v2 = v2>0.f ? v2+1.f : expf(v2); v3 = v3>0.f ? v3+1.f : expf(v3); \
            } else { v0*=(1.f/T_); v1*=(1.f/T_); v2*=(1.f/T_); v3*=(1.f/T_); } \
            OUTP[(size_t)(r0+nhw  )*C_ + mcol  ] = v0; \
            OUTP[(size_t)(r0+nhw+1)*C_ + mcol  ] = v1; \
            OUTP[(size_t)(r0+nhw  )*C_ + mcol+8] = v2; \
            OUTP[(size_t)(r0+nhw+1)*C_ + mcol+8] = v3; \
        } }

    // ---- Q ----
    ZACC();
    mma_blkW(acc, sWa, sX, 0,12,0,  m0,n0,gid,tig);
    __syncthreads(); fill_w16(sWau, Wk, C_, 0, 96, 0, tid); CPCOMMIT();   // G3
    CPWAIT(1); __syncthreads();                             // G2 done
    mma_blkW(acc, sWb, sX, 12,24,12, m0,n0,gid,tig);
    EPI(g_q, bq, 0);
    __syncthreads(); fill_w16(sWbu, Wk, C_, 96, 96, 0, tid); CPCOMMIT();  // G4
    CPWAIT(1); __syncthreads();                             // G3 done
    // ---- K ----
    ZACC();
    mma_blkW(acc, sWa, sX, 0,12,0,  m0,n0,gid,tig);
    __syncthreads(); fill_w16(sWau, Wv, C_, 0, 96, 0, tid); CPCOMMIT();   // G5
    CPWAIT(1); __syncthreads();                             // G4 done
    mma_blkW(acc, sWb, sX, 12,24,12, m0,n0,gid,tig);
    EPI(g_k, bk, 1);
    __syncthreads(); fill_w16(sWbu, Wv, C_, 96, 32, 0, tid); CPCOMMIT();  // G6
    CPWAIT(1); __syncthreads();                             // G5 done
    // ---- V ----
    ZACC();
    mma_blkW(acc, sWa, sX, 0,12,0,  m0,n0,gid,tig);
    CPWAIT(0); __syncthreads();                             // G6 done
    mma_blkW(acc, sWb, sX, 12,16,12, m0,n0,gid,tig);
    EPI(g_v, bv, 2);
    #undef ZACC
    #undef EPI
}

// ---------------- kernel 2: linear attention (unchanged from R14) --------
__global__ __launch_bounds__(128) void k_attn()
{
    __shared__ __align__(16) float pool[4224*2 + 256];
    float* pK    = pool;
    float* pV    = pool + 4224;
    float* sKsum = pool + 8448;
    float* sZ    = pool + 8448 + 128;
    const int n = blockIdx.x;
    const int tid = threadIdx.x;

    for (int s = 0; s < 32; s++) {
        pK[s*132 + tid] = g_k[(size_t)(s*N_ + n)*C_ + tid];
        pV[s*132 + tid] = g_v[(size_t)(s*N_ + n)*C_ + tid];
    }
    __syncthreads();

    const int h = tid >> 5, d = tid & 31;
    uint64_t kvp[16];
    #pragma unroll
    for (int i = 0; i < 16; i++) kvp[i] = 0ull;
    float ks = 0.f;
    for (int s = 0; s < 32; s++) {
        float kd = pK[s*132 + h*32 + d];
        ks += kd;
        uint64_t kdp; PACK2(kdp, kd, kd);
        const ulonglong2* vrow2 = (const ulonglong2*)&pV[s*132 + h*32];
        #pragma unroll
        for (int q = 0; q < 8; q++) {
            ulonglong2 vp = vrow2[q];
            FMA2(kvp[2*q  ], kdp, vp.x);
            FMA2(kvp[2*q+1], kdp, vp.y);
        }
    }
    __syncthreads();
    #pragma unroll
    for (int i = 0; i < 16; i++){
        float lo, hi; UNPACK2(lo, hi, kvp[i]);
        pV[h*1056 + d*33 + 2*i    ] = lo;
        pV[h*1056 + d*33 + 2*i + 1] = hi;
    }
    sKsum[tid] = ks;
    for (int s = 0; s < 32; s++)
        pK[s*132 + tid] = g_q[(size_t)(s*N_ + n)*C_ + tid];
    __syncthreads();
    {
        int tz = tid >> 2, hz = tid & 3;
        float z = 0.f;
        #pragma unroll
        for (int dd = 0; dd < 32; dd++)
            z += pK[tz*132 + hz*32 + dd] * sKsum[hz*32 + dd];
        sZ[tz*4 + hz] = (float)T_ / (z + 1e-6f);
    }
    __syncthreads();
    {
        const float* kvb = &pV[h*1056];
        uint64_t kvc[16];
        #pragma unroll
        for (int i = 0; i < 16; i++){
            float lo = kvb[(2*i  )*33 + d];
            float hi = kvb[(2*i+1)*33 + d];
            PACK2(kvc[i], lo, hi);
        }
        for (int tt = 0; tt < 32; tt++) {
            const uint64_t* qrow2 = (const uint64_t*)&pK[tt*132 + h*32];
            uint64_t accp = 0ull;
            #pragma unroll
            for (int i = 0; i < 16; i++)
                FMA2(accp, qrow2[i], kvc[i]);
            float alo, ahi; UNPACK2(alo, ahi, accp);
            g_at[(size_t)(tt*N_ + n)*C_ + tid] = (alo + ahi) * sZ[tt*4 + h];
        }
    }
}

// ---------------- kernel 3: FFN, interleaved B-operands ------------------
// 512 thr, 16 warps (8 wm x 2 wn), 128-row tile.
// smem floats: sOH[17408] (O [128][136], then H interleaved [64][272])
//              sU[17408] (interleaved [64][272]) | sWa[8704] | sWb[8704] | stats
__global__ __launch_bounds__(512) void k_ffn_tc(
    const float* __restrict__ x,
    const float* __restrict__ l1g, const float* __restrict__ l1b,
    const float* __restrict__ l2g, const float* __restrict__ l2b,
    const float* __restrict__ W1,  const float* __restrict__ b1f,
    const float* __restrict__ W2,  const float* __restrict__ b2f,
    float* __restrict__ out)
{
    extern __shared__ float sm[];
    float* sOH = sm;
    float* sU  = sm + 17408;
    float* sWa = sm + 34816;
    float* sWb = sm + 43520;
    float* sM2 = sm + 52224;
    float* sR2 = sm + 52352;
    const uint32_t sWau = (uint32_t)__cvta_generic_to_shared(sWa);
    const uint32_t sWbu = (uint32_t)__cvta_generic_to_shared(sWb);

    const int tid = threadIdx.x;
    const int lane = tid & 31, wid = tid >> 5;
    const int wm = wid >> 1, wn = wid & 1;
    const int gid = lane >> 2, tig = lane & 3;
    const int m0 = wm*16, n0 = wn*64;

    const int r0 = blockIdx.x * 128;
    const int t  = r0 / N_,  nn0 = r0 % N_;
    const int b  = nn0 / HW_, hw0 = nn0 % HW_;

    // pre-issue W1(jc=0) halves so they land during the prologue
    fill_w16(sWau, W1, F_, 0,  64, 0, tid); CPCOMMIT();   // G0
    fill_w16(sWbu, W1, F_, 64, 64, 0, tid); CPCOMMIT();   // G1

    // ---- prologue: sOH[row][c] = attn + ln1(x) ----
    {
        const int cc = (tid & 31) * 4;
        const int rb = tid >> 5;               // 0..15
        for (int j = 0; j < 8; j++) {
            int row = rb + 16*j;
            float4 a = *(const float4*)&g_at[(size_t)(r0+row)*C_ + cc];
            *(float4*)&sOH[row*KNP + cc] = a;
        }
    }
    __syncthreads();
    {
        const int rl = tid & 127, cq = tid >> 7;
        const float mu = g_mu[r0+rl], rs = g_rs[r0+rl];
        const float* xb = x + (size_t)(b*T_+t)*C_*HW_ + hw0 + rl;
        for (int c = cq; c < C_; c += 4)
            sOH[rl*KNP + c] += (xb[(size_t)c*HW_] - mu)*rs*l1g[c] + l1b[c];
    }
    __syncthreads();
    if (tid < 128) {   // ln2 stats, rotated (conflict-free)
        float s = 0.f, s2 = 0.f;
        for (int i = 0; i < 128; i++){
            int c = (i + tid) & 127;
            float v = sOH[tid*KNP + c]; s += v; s2 += v*v;
        }
        float mu = s*(1.f/C_);
        sM2[tid] = mu;
        sR2[tid] = rsqrtf(s2*(1.f/C_) - mu*mu + 1e-5f);
    }
    __syncthreads();
    {   // sU interleaved: element (k=c, n=rl) at [R(c)][rl*2+bit(c)]
        const int rl = tid & 127, q = tid >> 7;
        const float mu = sM2[rl], rs = sR2[rl];
        for (int i = 0; i < 32; i++){
            int c = q*32 + ((i + rl) & 31);
            float v = (sOH[rl*KNP + c] - mu)*rs*l2g[c] + l2b[c];
            sU[(((c>>3)<<2) + (c&3))*UP_ + rl*2 + ((c>>2)&1)] = rna(v);
        }
    }
    // acc2 = O + b2 in D-fragment layout (m=outcol, n=row)
    float acc2[8][4];
    {
        const int mcol = m0 + gid;
        const float bs0 = b2f[mcol], bs8 = b2f[mcol+8];
        #pragma unroll
        for (int j = 0; j < 8; j++){
            const int nhw = n0 + j*8 + 2*tig;
            acc2[j][0] = sOH[(nhw  )*KNP + mcol  ] + bs0;
            acc2[j][1] = sOH[(nhw+1)*KNP + mcol  ] + bs0;
            acc2[j][2] = sOH[(nhw  )*KNP + mcol+8] + bs8;
            acc2[j][3] = sOH[(nhw+1)*KNP + mcol+8] + bs8;
        }
    }
    __syncthreads();   // sU ready; acc2-init reads of sOH done

    float acc1[8][4];
    for (int jc = 0; jc < 4; jc++) {
        CPWAIT(1); __syncthreads();            // W1 lo ready
        {
            const float bs0 = b1f[jc*128 + m0 + gid];
            const float bs8 = b1f[jc*128 + m0 + gid + 8];
            #pragma unroll
            for (int j = 0; j < 8; j++){
                acc1[j][0] = bs0; acc1[j][1] = bs0;
                acc1[j][2] = bs8; acc1[j][3] = bs8;
            }
        }
        mma_blkI(acc1, sWa, sU, 0,8,0,  m0,n0,gid,tig);
        __syncthreads(); fill_w16(sWau, W2, C_, jc*128,     64, 0, tid); CPCOMMIT();
        CPWAIT(1); __syncthreads();            // W1 hi ready
        mma_blkI(acc1, sWb, sU, 8,16,8, m0,n0,gid,tig);
        // gelu -> sOH as H interleaved: element (k=mloc, n=nhw)
        {
            const int mloc = m0 + gid;
            const int Rm = ((mloc>>3)<<2) + (mloc&3);
            const int bm = (mloc>>2)&1;
            float* h0 = &sOH[Rm*UP_ + bm];          // k = mloc
            float* h8 = &sOH[(Rm+4)*UP_ + bm];      // k = mloc+8
            #pragma unroll
            for (int j = 0; j < 8; j++){
                const int nhw = n0 + j*8 + 2*tig;
                float g0 = acc1[j][0], g1 = acc1[j][1];
                float g2 = acc1[j][2], g3 = acc1[j][3];
                g0 = rna(0.5f*g0*(1.f + erff(g0*0.70710678118f)));
                g1 = rna(0.5f*g1*(1.f + erff(g1*0.70710678118f)));
                g2 = rna(0.5f*g2*(1.f + erff(g2*0.70710678118f)));
                g3 = rna(0.5f*g3*(1.f + erff(g3*0.70710678118f)));
                h0[(nhw  )*2] = g0;
                h0[(nhw+1)*2] = g1;
                h8[(nhw  )*2] = g2;
                h8[(nhw+1)*2] = g3;
            }
        }
        __syncthreads(); fill_w16(sWbu, W2, C_, jc*128+64,  64, 0, tid); CPCOMMIT();
        CPWAIT(1); __syncthreads();            // W2 lo ready
        mma_blkI(acc2, sWa, sOH, 0,8,0,  m0,n0,gid,tig);
        __syncthreads();
        if (jc < 3){ fill_w16(sWau, W1, F_, 0,  64, (jc+1)*128, tid); CPCOMMIT(); }
        if (jc < 3){ CPWAIT(1); } else { CPWAIT(0); }
        __syncthreads();                       // W2 hi ready
        mma_blkI(acc2, sWb, sOH, 8,16,8, m0,n0,gid,tig);
        __syncthreads();
        if (jc < 3){ fill_w16(sWbu, W1, F_, 64, 64, (jc+1)*128, tid); CPCOMMIT(); }
    }

    // ---- epilogue: transposed writeback, consecutive-hw float2 ----
    {
        float* obase = out + (size_t)(b*T_+t)*C_*HW_ + hw0;
        const int mcol = m0 + gid;
        #pragma unroll
        for (int j = 0; j < 8; j++){
            const int nhw = n0 + j*8 + 2*tig;
            *(float2*)&obase[(size_t)(mcol  )*HW_ + nhw] = make_float2(acc2[j][0], acc2[j][1]);
            *(float2*)&obase[(size_t)(mcol+8)*HW_ + nhw] = make_float2(acc2[j][2], acc2[j][3]);
        }
    }
}

// ---------------- launch --------------------------------------------------
extern "C" void kernel_launch(void* const* d_in, const int* in_sizes, int n_in,
                              void* d_out, int out_size)
{
    (void)in_sizes; (void)n_in; (void)out_size;
    const float* x   = (const float*)d_in[0];
    const float* gd  = (const float*)d_in[1];
    const float* Wq  = (const float*)d_in[2];
    const float* bq  = (const float*)d_in[3];
    const float* Wk  = (const float*)d_in[4];
    const float* bk  = (const float*)d_in[5];
    const float* Wv  = (const float*)d_in[6];
    const float* bv  = (const float*)d_in[7];
    const float* l1g = (const float*)d_in[8];
    const float* l1b = (const float*)d_in[9];
    const float* l2g = (const float*)d_in[10];
    const float* l2b = (const float*)d_in[11];
    const float* W1  = (const float*)d_in[12];
    const float* b1  = (const float*)d_in[13];
    const float* W2  = (const float*)d_in[14];
    const float* b2  = (const float*)d_in[15];
    float* out = (float*)d_out;

    const int smemQkv = (192*KNP + 2*96*KNP) * 4;         // 208,896 B
    const int smemFfn = (2*17408 + 2*8704 + 256) * 4;     // 209,920 B
    cudaFuncSetAttribute(k_qkv_tc, cudaFuncAttributeMaxDynamicSharedMemorySize, smemQkv);
    cudaFuncSetAttribute(k_ffn_tc, cudaFuncAttributeMaxDynamicSharedMemorySize, smemFfn);

    k_qkv_tc<<<M_/128, 512, smemQkv>>>(x, gd, Wq, bq, Wk, bk, Wv, bv);
    k_attn  <<<N_, 128>>>();
    k_ffn_tc<<<M_/128, 512, smemFfn>>>(x, l1g, l1b, l2g, l2b, W1, b1, W2, b2, out);
}

// round 16
// speedup vs baseline: 1.1789x; 1.1789x over previous
#include <cuda_runtime.h>
#include <math.h>
#include <stdint.h>

#define B_  4
#define T_  32
#define C_  128
#define HW_ 1024
#define N_  4096
#define GD_ 64
#define M_  (T_*N_)      // 131072 rows, r = t*N_ + n
#define F_  512
#define KNP 136          // universal k-major pad

// ---------------- scratch (device globals; no allocation) ----------------
static __device__ float g_mu[M_];
static __device__ float g_rs[M_];
static __device__ float g_q [(size_t)M_*C_];
static __device__ float g_k [(size_t)M_*C_];
static __device__ float g_v [(size_t)M_*C_];
static __device__ float g_at[(size_t)M_*C_];

// ---------------- helpers -------------------------------------------------
#define CP16(dst, src) asm volatile("cp.async.cg.shared.global [%0], [%1], 16;" \
                                    :: "r"(dst), "l"(src) : "memory")
#define CPCOMMIT()    asm volatile("cp.async.commit_group;" ::: "memory")
#define CPWAIT(n)     asm volatile("cp.async.wait_group %0;" :: "n"(n) : "memory")

#define FMA2(d, a, b)  asm("fma.rn.f32x2 %0, %1, %2, %0;" : "+l"(d) : "l"(a), "l"(b))
#define PACK2(d, lo, hi) asm("mov.b64 %0, {%1,%2};" : "=l"(d) : "f"(lo), "f"(hi))
#define UNPACK2(lo, hi, s) asm("mov.b64 {%0,%1}, %2;" : "=f"(lo), "=f"(hi) : "l"(s))

__device__ __forceinline__ float rna(float f){
    float r; asm("cvt.rna.tf32.f32 %0, %1;" : "=f"(r) : "f"(f)); return r;
}
__device__ __forceinline__ void mma8(float* d, const uint32_t* a,
                                     uint32_t b0, uint32_t b1){
    asm volatile(
        "mma.sync.aligned.m16n8k8.row.col.f32.tf32.tf32.f32 "
        "{%0,%1,%2,%3}, {%4,%5,%6,%7}, {%8,%9}, {%0,%1,%2,%3};"
        : "+f"(d[0]), "+f"(d[1]), "+f"(d[2]), "+f"(d[3])
        : "r"(a[0]), "r"(a[1]), "r"(a[2]), "r"(a[3]), "r"(b0), "r"(b1));
}
// 16B cp.async fill into [k][n] pad-KNP layout (512 threads), 128 n-cols.
__device__ __forceinline__ void fill_w16(uint32_t sbase,
                                         const float* __restrict__ W, size_t ldw,
                                         int kbeg, int kcnt, int col0, int tid)
{
    const int k0 = tid >> 5, n16 = (tid & 31) * 4;
    for (int p = 0; p < kcnt/16; p++){
        int k = k0 + 16*p;
        CP16(sbase + (uint32_t)(k*KNP + n16)*4u,
             W + (size_t)(kbeg + k)*ldw + col0 + n16);
    }
}
// MMA: A = weights [k][m] (local k), B = activations [k][n] (global k).
// Warp tile: m16 x n64. D[m][n]: m = weight col, n = row.
__device__ __forceinline__ void mma_blkW(
    float acc[][4], const float* __restrict__ sW,
    const float* __restrict__ sB,
    int ks0, int ks1, int kloc0, int m0, int n0, int gid, int tig)
{
    #pragma unroll 2
    for (int ks = ks0; ks < ks1; ks++){
        const int kA = (ks - kloc0)*8;
        const int kB = ks*8;
        uint32_t a[4];
        a[0] = __float_as_uint(sW[(kA+tig  )*KNP + m0 + gid    ]);
        a[1] = __float_as_uint(sW[(kA+tig  )*KNP + m0 + gid + 8]);
        a[2] = __float_as_uint(sW[(kA+tig+4)*KNP + m0 + gid    ]);
        a[3] = __float_as_uint(sW[(kA+tig+4)*KNP + m0 + gid + 8]);
        #pragma unroll
        for (int j = 0; j < 8; j++){
            const int nb = n0 + j*8 + gid;
            uint32_t b0 = __float_as_uint(sB[(kB+tig  )*KNP + nb]);
            uint32_t b1 = __float_as_uint(sB[(kB+tig+4)*KNP + nb]);
            mma8(acc[j], a, b0, b1);
        }
    }
}

// ---------------- kernel 1: merged QKV GEMM + ln1 stats ------------------
// 512 thr, 16 warps (8 wm over weight-cols x 2 wn over rows).
// smem floats: sX[192*136] | sWa[96*136] | sWb[96*136]
__global__ __launch_bounds__(512) void k_qkv_tc(
    const float* __restrict__ x, const float* __restrict__ gdn,
    const float* __restrict__ Wq, const float* __restrict__ bq,
    const float* __restrict__ Wk, const float* __restrict__ bk,
    const float* __restrict__ Wv, const float* __restrict__ bv)
{
    extern __shared__ float sm[];
    float* sX  = sm;
    float* sWa = sm + 26112;
    float* sWb = sm + 39168;
    const uint32_t sXu  = (uint32_t)__cvta_generic_to_shared(sX);
    const uint32_t sWau = (uint32_t)__cvta_generic_to_shared(sWa);
    const uint32_t sWbu = (uint32_t)__cvta_generic_to_shared(sWb);

    const int tid = threadIdx.x;
    const int lane = tid & 31, wid = tid >> 5;
    const int wm = wid >> 1, wn = wid & 1;
    const int gid = lane >> 2, tig = lane & 3;
    const int m0 = wm*16, n0 = wn*64;

    const int r0 = blockIdx.x * 128;
    const int t  = r0 / N_,  nn0 = r0 % N_;
    const int b  = nn0 / HW_, hw0 = nn0 % HW_;
    const float* xbt = x   + (size_t)(b*T_ + t) * C_ * HW_;
    const float* gbt = gdn + (size_t)(b*T_ + t) * GD_;

    // fill B = x tile [c][hw], native layout, all CP16
    {
        const int hw4 = (tid & 31)*4, c0 = tid >> 5;
        for (int p = 0; p < 8; p++){
            int c = c0 + 16*p;
            CP16(sXu + (uint32_t)(c*KNP + hw4)*4u,
                 xbt + (size_t)c*HW_ + hw0 + hw4);
        }
    }
    // guidance rows 128..191: broadcast per row (plain stores)
    for (int p = 0; p < 4; p++){
        int i = tid + 512*p;
        int grow = i >> 5, col4 = (i & 31)*4;
        float gv = gbt[grow];
        float4 f4 = make_float4(gv, gv, gv, gv);
        *(float4*)&sX[(128+grow)*KNP + col4] = f4;
    }
    CPCOMMIT();                                             // G0
    fill_w16(sWau, Wq, C_, 0,  96, 0, tid); CPCOMMIT();     // G1
    fill_w16(sWbu, Wq, C_, 96, 96, 0, tid); CPCOMMIT();     // G2
    CPWAIT(1); __syncthreads();   // <=1 pending => G0 AND G1 done

    // ln1 stats: column hw = tid over c (conflict-free: banks 8c+hw)
    if (tid < 128){
        float s = 0.f, s2 = 0.f;
        for (int c = 0; c < 128; c++){ float v = sX[c*KNP + tid]; s += v; s2 += v*v; }
        float mu = s * (1.0f/C_);
        g_mu[r0+tid] = mu;
        g_rs[r0+tid] = rsqrtf(s2 * (1.0f/C_) - mu*mu + 1e-5f);
    }

    float acc[8][4];
    #define ZACC() { _Pragma("unroll") for(int j2=0;j2<8;j2++) \
                     _Pragma("unroll") for(int q2=0;q2<4;q2++) acc[j2][q2]=0.f; }
    // D[m=weightcol][n=row]: d0:(m,n) d1:(m,n+1) d2:(m+8,n) d3:(m+8,n+1)
    #define EPI(OUTP, BS, Y) { \
        const int mcol = m0 + gid; \
        const float bs0 = BS[mcol], bs8 = BS[mcol+8]; \
        _Pragma("unroll") for (int j = 0; j < 8; j++){ \
            const int nhw = n0 + j*8 + 2*tig; \
            float v0 = acc[j][0]+bs0, v1 = acc[j][1]+bs0; \
            float v2 = acc[j][2]+bs8, v3 = acc[j][3]+bs8; \
            if (Y < 2){ \
                v0 = v0>0.f ? v0+1.f : __expf(v0); v1 = v1>0.f ? v1+1.f : __expf(v1); \
                v2 = v2>0.f ? v2+1.f : __expf(v2); v3 = v3>0.f ? v3+1.f : __expf(v3); \
            } else { v0*=(1.f/T_); v1*=(1.f/T_); v2*=(1.f/T_); v3*=(1.f/T_); } \
            OUTP[(size_t)(r0+nhw  )*C_ + mcol  ] = v0; \
            OUTP[(size_t)(r0+nhw+1)*C_ + mcol  ] = v1; \
            OUTP[(size_t)(r0+nhw  )*C_ + mcol+8] = v2; \
            OUTP[(size_t)(r0+nhw+1)*C_ + mcol+8] = v3; \
        } }

    // ---- Q ----
    ZACC();
    mma_blkW(acc, sWa, sX, 0,12,0,  m0,n0,gid,tig);
    __syncthreads(); fill_w16(sWau, Wk, C_, 0, 96, 0, tid); CPCOMMIT();   // G3
    CPWAIT(1); __syncthreads();                             // G2 done
    mma_blkW(acc, sWb, sX, 12,24,12, m0,n0,gid,tig);
    EPI(g_q, bq, 0);
    __syncthreads(); fill_w16(sWbu, Wk, C_, 96, 96, 0, tid); CPCOMMIT();  // G4
    CPWAIT(1); __syncthreads();                             // G3 done
    // ---- K ----
    ZACC();
    mma_blkW(acc, sWa, sX, 0,12,0,  m0,n0,gid,tig);
    __syncthreads(); fill_w16(sWau, Wv, C_, 0, 96, 0, tid); CPCOMMIT();   // G5
    CPWAIT(1); __syncthreads();                             // G4 done
    mma_blkW(acc, sWb, sX, 12,24,12, m0,n0,gid,tig);
    EPI(g_k, bk, 1);
    __syncthreads(); fill_w16(sWbu, Wv, C_, 96, 32, 0, tid); CPCOMMIT();  // G6
    CPWAIT(1); __syncthreads();                             // G5 done
    // ---- V ----
    ZACC();
    mma_blkW(acc, sWa, sX, 0,12,0,  m0,n0,gid,tig);
    CPWAIT(0); __syncthreads();                             // G6 done
    mma_blkW(acc, sWb, sX, 12,16,12, m0,n0,gid,tig);
    EPI(g_v, bv, 2);
    #undef ZACC
    #undef EPI
}

// ---------------- kernel 2: linear attention, f32x2-packed FMAs ----------
__global__ __launch_bounds__(128) void k_attn()
{
    __shared__ __align__(16) float pool[4224*2 + 256];
    float* pK    = pool;
    float* pV    = pool + 4224;
    float* sKsum = pool + 8448;
    float* sZ    = pool + 8448 + 128;
    const int n = blockIdx.x;
    const int tid = threadIdx.x;

    for (int s = 0; s < 32; s++) {
        pK[s*132 + tid] = g_k[(size_t)(s*N_ + n)*C_ + tid];
        pV[s*132 + tid] = g_v[(size_t)(s*N_ + n)*C_ + tid];
    }
    __syncthreads();

    const int h = tid >> 5, d = tid & 31;
    uint64_t kvp[16];
    #pragma unroll
    for (int i = 0; i < 16; i++) kvp[i] = 0ull;
    float ks = 0.f;
    for (int s = 0; s < 32; s++) {
        float kd = pK[s*132 + h*32 + d];
        ks += kd;
        uint64_t kdp; PACK2(kdp, kd, kd);
        const ulonglong2* vrow2 = (const ulonglong2*)&pV[s*132 + h*32];
        #pragma unroll
        for (int q = 0; q < 8; q++) {
            ulonglong2 vp = vrow2[q];
            FMA2(kvp[2*q  ], kdp, vp.x);
            FMA2(kvp[2*q+1], kdp, vp.y);
        }
    }
    __syncthreads();
    #pragma unroll
    for (int i = 0; i < 16; i++){
        float lo, hi; UNPACK2(lo, hi, kvp[i]);
        pV[h*1056 + d*33 + 2*i    ] = lo;
        pV[h*1056 + d*33 + 2*i + 1] = hi;
    }
    sKsum[tid] = ks;
    for (int s = 0; s < 32; s++)
        pK[s*132 + tid] = g_q[(size_t)(s*N_ + n)*C_ + tid];
    __syncthreads();
    {
        int tz = tid >> 2, hz = tid & 3;
        float z = 0.f;
        #pragma unroll
        for (int dd = 0; dd < 32; dd++)
            z += pK[tz*132 + hz*32 + dd] * sKsum[hz*32 + dd];
        sZ[tz*4 + hz] = (float)T_ / (z + 1e-6f);
    }
    __syncthreads();
    {
        const float* kvb = &pV[h*1056];
        uint64_t kvc[16];
        #pragma unroll
        for (int i = 0; i < 16; i++){
            float lo = kvb[(2*i  )*33 + d];
            float hi = kvb[(2*i+1)*33 + d];
            PACK2(kvc[i], lo, hi);
        }
        for (int tt = 0; tt < 32; tt++) {
            const uint64_t* qrow2 = (const uint64_t*)&pK[tt*132 + h*32];
            uint64_t accp = 0ull;
            #pragma unroll
            for (int i = 0; i < 16; i++)
                FMA2(accp, qrow2[i], kvc[i]);
            float alo, ahi; UNPACK2(alo, ahi, accp);
            g_at[(size_t)(tt*N_ + n)*C_ + tid] = (alo + ahi) * sZ[tt*4 + h];
        }
    }
}

// ---------------- kernel 3: FFN, all-native k-major (R10/R14 config) -----
// 512 thr, 16 warps (8 wm over out/ffn cols x 2 wn over rows), 128-row tile.
__global__ __launch_bounds__(512) void k_ffn_tc(
    const float* __restrict__ x,
    const float* __restrict__ l1g, const float* __restrict__ l1b,
    const float* __restrict__ l2g, const float* __restrict__ l2b,
    const float* __restrict__ W1,  const float* __restrict__ b1f,
    const float* __restrict__ W2,  const float* __restrict__ b2f,
    float* __restrict__ out)
{
    extern __shared__ float sm[];
    float* sOH = sm;
    float* sU  = sm + 17408;
    float* sWa = sm + 34816;
    float* sWb = sm + 43520;
    float* sM2 = sm + 52224;
    float* sR2 = sm + 52352;
    const uint32_t sWau = (uint32_t)__cvta_generic_to_shared(sWa);
    const uint32_t sWbu = (uint32_t)__cvta_generic_to_shared(sWb);

    const int tid = threadIdx.x;
    const int lane = tid & 31, wid = tid >> 5;
    const int wm = wid >> 1, wn = wid & 1;
    const int gid = lane >> 2, tig = lane & 3;
    const int m0 = wm*16, n0 = wn*64;

    const int r0 = blockIdx.x * 128;
    const int t  = r0 / N_,  nn0 = r0 % N_;
    const int b  = nn0 / HW_, hw0 = nn0 % HW_;

    // pre-issue W1(jc=0) halves so they land during the prologue
    fill_w16(sWau, W1, F_, 0,  64, 0, tid); CPCOMMIT();   // G0
    fill_w16(sWbu, W1, F_, 64, 64, 0, tid); CPCOMMIT();   // G1

    // ---- prologue: sOH[row][c] = attn + ln1(x) ----
    {
        const int cc = (tid & 31) * 4;
        const int rb = tid >> 5;               // 0..15
        for (int j = 0; j < 8; j++) {
            int row = rb + 16*j;
            float4 a = *(const float4*)&g_at[(size_t)(r0+row)*C_ + cc];
            *(float4*)&sOH[row*KNP + cc] = a;
        }
    }
    __syncthreads();
    {
        const int rl = tid & 127, cq = tid >> 7;
        const float mu = g_mu[r0+rl], rs = g_rs[r0+rl];
        const float* xb = x + (size_t)(b*T_+t)*C_*HW_ + hw0 + rl;
        for (int c = cq; c < C_; c += 4)
            sOH[rl*KNP + c] += (xb[(size_t)c*HW_] - mu)*rs*l1g[c] + l1b[c];
    }
    __syncthreads();
    if (tid < 128) {   // ln2 stats, rotated (conflict-free)
        float s = 0.f, s2 = 0.f;
        for (int i = 0; i < 128; i++){
            int c = (i + tid) & 127;
            float v = sOH[tid*KNP + c]; s += v; s2 += v*v;
        }
        float mu = s*(1.f/C_);
        sM2[tid] = mu;
        sR2[tid] = rsqrtf(s2*(1.f/C_) - mu*mu + 1e-5f);
    }
    __syncthreads();
    {   // sU[c][row] = tf32(ln2(O)) — transposed, rotated (conflict-free)
        const int rl = tid & 127, q = tid >> 7;
        const float mu = sM2[rl], rs = sR2[rl];
        for (int i = 0; i < 32; i++){
            int c = q*32 + ((i + rl) & 31);
            float v = (sOH[rl*KNP + c] - mu)*rs*l2g[c] + l2b[c];
            sU[c*KNP + rl] = rna(v);
        }
    }
    // acc2 = O + b2 in D-fragment layout (m=outcol, n=row)
    float acc2[8][4];
    {
        const int mcol = m0 + gid;
        const float bs0 = b2f[mcol], bs8 = b2f[mcol+8];
        #pragma unroll
        for (int j = 0; j < 8; j++){
            const int nhw = n0 + j*8 + 2*tig;
            acc2[j][0] = sOH[(nhw  )*KNP + mcol  ] + bs0;
            acc2[j][1] = sOH[(nhw+1)*KNP + mcol  ] + bs0;
            acc2[j][2] = sOH[(nhw  )*KNP + mcol+8] + bs8;
            acc2[j][3] = sOH[(nhw+1)*KNP + mcol+8] + bs8;
        }
    }
    __syncthreads();   // sU ready; acc2-init reads of sOH done

    float acc1[8][4];
    for (int jc = 0; jc < 4; jc++) {
        CPWAIT(1); __syncthreads();            // W1 lo ready
        {
            const float bs0 = b1f[jc*128 + m0 + gid];
            const float bs8 = b1f[jc*128 + m0 + gid + 8];
            #pragma unroll
            for (int j = 0; j < 8; j++){
                acc1[j][0] = bs0; acc1[j][1] = bs0;
                acc1[j][2] = bs8; acc1[j][3] = bs8;
            }
        }
        mma_blkW(acc1, sWa, sU, 0,8,0,  m0,n0,gid,tig);
        __syncthreads(); fill_w16(sWau, W2, C_, jc*128,     64, 0, tid); CPCOMMIT();
        CPWAIT(1); __syncthreads();            // W1 hi ready
        mma_blkW(acc1, sWb, sU, 8,16,8, m0,n0,gid,tig);
        // gelu -> sOH as H[ffncol][row] (native B layout for GEMM2)
        {
            const int mloc = m0 + gid;
            #pragma unroll
            for (int j = 0; j < 8; j++){
                const int nhw = n0 + j*8 + 2*tig;
                float g0 = acc1[j][0], g1 = acc1[j][1];
                float g2 = acc1[j][2], g3 = acc1[j][3];
                g0 = rna(0.5f*g0*(1.f + erff(g0*0.70710678118f)));
                g1 = rna(0.5f*g1*(1.f + erff(g1*0.70710678118f)));
                g2 = rna(0.5f*g2*(1.f + erff(g2*0.70710678118f)));
                g3 = rna(0.5f*g3*(1.f + erff(g3*0.70710678118f)));
                *(float2*)&sOH[(mloc  )*KNP + nhw] = make_float2(g0, g1);
                *(float2*)&sOH[(mloc+8)*KNP + nhw] = make_float2(g2, g3);
            }
        }
        __syncthreads(); fill_w16(sWbu, W2, C_, jc*128+64,  64, 0, tid); CPCOMMIT();
        CPWAIT(1); __syncthreads();            // W2 lo ready
        mma_blkW(acc2, sWa, sOH, 0,8,0,  m0,n0,gid,tig);
        __syncthreads();
        if (jc < 3){ fill_w16(sWau, W1, F_, 0,  64, (jc+1)*128, tid); CPCOMMIT(); }
        if (jc < 3){ CPWAIT(1); } else { CPWAIT(0); }
        __syncthreads();                       // W2 hi ready
        mma_blkW(acc2, sWb, sOH, 8,16,8, m0,n0,gid,tig);
        __syncthreads();
        if (jc < 3){ fill_w16(sWbu, W1, F_, 64, 64, (jc+1)*128, tid); CPCOMMIT(); }
    }

    // ---- epilogue: transposed writeback, consecutive-hw float2 ----
    {
        float* obase = out + (size_t)(b*T_+t)*C_*HW_ + hw0;
        const int mcol = m0 + gid;
        #pragma unroll
        for (int j = 0; j < 8; j++){
            const int nhw = n0 + j*8 + 2*tig;
            *(float2*)&obase[(size_t)(mcol  )*HW_ + nhw] = make_float2(acc2[j][0], acc2[j][1]);
            *(float2*)&obase[(size_t)(mcol+8)*HW_ + nhw] = make_float2(acc2[j][2], acc2[j][3]);
        }
    }
}

// ---------------- launch --------------------------------------------------
extern "C" void kernel_launch(void* const* d_in, const int* in_sizes, int n_in,
                              void* d_out, int out_size)
{
    (void)in_sizes; (void)n_in; (void)out_size;
    const float* x   = (const float*)d_in[0];
    const float* gd  = (const float*)d_in[1];
    const float* Wq  = (const float*)d_in[2];
    const float* bq  = (const float*)d_in[3];
    const float* Wk  = (const float*)d_in[4];
    const float* bk  = (const float*)d_in[5];
    const float* Wv  = (const float*)d_in[6];
    const float* bv  = (const float*)d_in[7];
    const float* l1g = (const float*)d_in[8];
    const float* l1b = (const float*)d_in[9];
    const float* l2g = (const float*)d_in[10];
    const float* l2b = (const float*)d_in[11];
    const float* W1  = (const float*)d_in[12];
    const float* b1  = (const float*)d_in[13];
    const float* W2  = (const float*)d_in[14];
    const float* b2  = (const float*)d_in[15];
    float* out = (float*)d_out;

    const int smemQkv = (192*KNP + 2*96*KNP) * 4;         // 208,896 B
    const int smemFfn = (2*128*KNP + 2*64*KNP + 256) * 4; // 209,920 B
    cudaFuncSetAttribute(k_qkv_tc, cudaFuncAttributeMaxDynamicSharedMemorySize, smemQkv);
    cudaFuncSetAttribute(k_ffn_tc, cudaFuncAttributeMaxDynamicSharedMemorySize, smemFfn);

    k_qkv_tc<<<M_/128, 512, smemQkv>>>(x, gd, Wq, bq, Wk, bk, Wv, bv);
    k_attn  <<<N_, 128>>>();
    k_ffn_tc<<<M_/128, 512, smemFfn>>>(x, l1g, l1b, l2g, l2b, W1, b1, W2, b2, out);
}

// round 17
// speedup vs baseline: 1.2582x; 1.0673x over previous
#include <cuda_runtime.h>
#include <math.h>
#include <stdint.h>

#define B_  4
#define T_  32
#define C_  128
#define HW_ 1024
#define N_  4096
#define GD_ 64
#define M_  (T_*N_)      // 131072 rows, r = t*N_ + n
#define F_  512
#define KNP 136          // universal k-major pad

// ---------------- scratch (device globals; no allocation) ----------------
static __device__ float g_mu[M_];
static __device__ float g_rs[M_];
static __device__ float g_q [(size_t)M_*C_];
static __device__ float g_k [(size_t)M_*C_];
static __device__ float g_v [(size_t)M_*C_];
static __device__ float g_at[(size_t)M_*C_];

// ---------------- helpers -------------------------------------------------
#define CP16(dst, src) asm volatile("cp.async.cg.shared.global [%0], [%1], 16;" \
                                    :: "r"(dst), "l"(src) : "memory")
#define CPCOMMIT()    asm volatile("cp.async.commit_group;" ::: "memory")
#define CPWAIT(n)     asm volatile("cp.async.wait_group %0;" :: "n"(n) : "memory")

#define FMA2(d, a, b)  asm("fma.rn.f32x2 %0, %1, %2, %0;" : "+l"(d) : "l"(a), "l"(b))
#define PACK2(d, lo, hi) asm("mov.b64 %0, {%1,%2};" : "=l"(d) : "f"(lo), "f"(hi))
#define UNPACK2(lo, hi, s) asm("mov.b64 {%0,%1}, %2;" : "=f"(lo), "=f"(hi) : "l"(s))

__device__ __forceinline__ float rna(float f){
    float r; asm("cvt.rna.tf32.f32 %0, %1;" : "=f"(r) : "f"(f)); return r;
}
// fast GELU: tanh formulation with HW MUFU.TANH (sm_75+)
__device__ __forceinline__ float gelu_fast(float v){
    float u = 0.7978845608f * v * (1.f + 0.044715f * v * v);
    float th; asm("tanh.approx.f32 %0, %1;" : "=f"(th) : "f"(u));
    return 0.5f * v * (1.f + th);
}
__device__ __forceinline__ void mma8(float* d, const uint32_t* a,
                                     uint32_t b0, uint32_t b1){
    asm volatile(
        "mma.sync.aligned.m16n8k8.row.col.f32.tf32.tf32.f32 "
        "{%0,%1,%2,%3}, {%4,%5,%6,%7}, {%8,%9}, {%0,%1,%2,%3};"
        : "+f"(d[0]), "+f"(d[1]), "+f"(d[2]), "+f"(d[3])
        : "r"(a[0]), "r"(a[1]), "r"(a[2]), "r"(a[3]), "r"(b0), "r"(b1));
}
// 16B cp.async fill into [k][n] pad-KNP layout (512 threads), 128 n-cols.
__device__ __forceinline__ void fill_w16(uint32_t sbase,
                                         const float* __restrict__ W, size_t ldw,
                                         int kbeg, int kcnt, int col0, int tid)
{
    const int k0 = tid >> 5, n16 = (tid & 31) * 4;
    for (int p = 0; p < kcnt/16; p++){
        int k = k0 + 16*p;
        CP16(sbase + (uint32_t)(k*KNP + n16)*4u,
             W + (size_t)(kbeg + k)*ldw + col0 + n16);
    }
}
// MMA: A = weights [k][m] (local k), B = activations [k][n] (global k).
// Warp tile: m16 x n64. D[m][n]: m = weight col, n = row.
__device__ __forceinline__ void mma_blkW(
    float acc[][4], const float* __restrict__ sW,
    const float* __restrict__ sB,
    int ks0, int ks1, int kloc0, int m0, int n0, int gid, int tig)
{
    #pragma unroll 2
    for (int ks = ks0; ks < ks1; ks++){
        const int kA = (ks - kloc0)*8;
        const int kB = ks*8;
        uint32_t a[4];
        a[0] = __float_as_uint(sW[(kA+tig  )*KNP + m0 + gid    ]);
        a[1] = __float_as_uint(sW[(kA+tig  )*KNP + m0 + gid + 8]);
        a[2] = __float_as_uint(sW[(kA+tig+4)*KNP + m0 + gid    ]);
        a[3] = __float_as_uint(sW[(kA+tig+4)*KNP + m0 + gid + 8]);
        #pragma unroll
        for (int j = 0; j < 8; j++){
            const int nb = n0 + j*8 + gid;
            uint32_t b0 = __float_as_uint(sB[(kB+tig  )*KNP + nb]);
            uint32_t b1 = __float_as_uint(sB[(kB+tig+4)*KNP + nb]);
            mma8(acc[j], a, b0, b1);
        }
    }
}

// ---------------- kernel 1: merged QKV GEMM + ln1 stats ------------------
// 512 thr, 16 warps (8 wm over weight-cols x 2 wn over rows).
// smem floats: sX[192*136] | sWa[96*136] | sWb[96*136]
__global__ __launch_bounds__(512) void k_qkv_tc(
    const float* __restrict__ x, const float* __restrict__ gdn,
    const float* __restrict__ Wq, const float* __restrict__ bq,
    const float* __restrict__ Wk, const float* __restrict__ bk,
    const float* __restrict__ Wv, const float* __restrict__ bv)
{
    extern __shared__ float sm[];
    float* sX  = sm;
    float* sWa = sm + 26112;
    float* sWb = sm + 39168;
    const uint32_t sXu  = (uint32_t)__cvta_generic_to_shared(sX);
    const uint32_t sWau = (uint32_t)__cvta_generic_to_shared(sWa);
    const uint32_t sWbu = (uint32_t)__cvta_generic_to_shared(sWb);

    const int tid = threadIdx.x;
    const int lane = tid & 31, wid = tid >> 5;
    const int wm = wid >> 1, wn = wid & 1;
    const int gid = lane >> 2, tig = lane & 3;
    const int m0 = wm*16, n0 = wn*64;

    const int r0 = blockIdx.x * 128;
    const int t  = r0 / N_,  nn0 = r0 % N_;
    const int b  = nn0 / HW_, hw0 = nn0 % HW_;
    const float* xbt = x   + (size_t)(b*T_ + t) * C_ * HW_;
    const float* gbt = gdn + (size_t)(b*T_ + t) * GD_;

    // fill B = x tile [c][hw], native layout, all CP16
    {
        const int hw4 = (tid & 31)*4, c0 = tid >> 5;
        for (int p = 0; p < 8; p++){
            int c = c0 + 16*p;
            CP16(sXu + (uint32_t)(c*KNP + hw4)*4u,
                 xbt + (size_t)c*HW_ + hw0 + hw4);
        }
    }
    // guidance rows 128..191: broadcast per row (plain stores)
    for (int p = 0; p < 4; p++){
        int i = tid + 512*p;
        int grow = i >> 5, col4 = (i & 31)*4;
        float gv = gbt[grow];
        float4 f4 = make_float4(gv, gv, gv, gv);
        *(float4*)&sX[(128+grow)*KNP + col4] = f4;
    }
    CPCOMMIT();                                             // G0
    fill_w16(sWau, Wq, C_, 0,  96, 0, tid); CPCOMMIT();     // G1
    fill_w16(sWbu, Wq, C_, 96, 96, 0, tid); CPCOMMIT();     // G2
    CPWAIT(1); __syncthreads();   // <=1 pending => G0 AND G1 done

    // ln1 stats: column hw = tid over c (conflict-free: banks 8c+hw)
    if (tid < 128){
        float s = 0.f, s2 = 0.f;
        for (int c = 0; c < 128; c++){ float v = sX[c*KNP + tid]; s += v; s2 += v*v; }
        float mu = s * (1.0f/C_);
        g_mu[r0+tid] = mu;
        g_rs[r0+tid] = rsqrtf(s2 * (1.0f/C_) - mu*mu + 1e-5f);
    }

    float acc[8][4];
    #define ZACC() { _Pragma("unroll") for(int j2=0;j2<8;j2++) \
                     _Pragma("unroll") for(int q2=0;q2<4;q2++) acc[j2][q2]=0.f; }
    // D[m=weightcol][n=row]: d0:(m,n) d1:(m,n+1) d2:(m+8,n) d3:(m+8,n+1)
    #define EPI(OUTP, BS, Y) { \
        const int mcol = m0 + gid; \
        const float bs0 = BS[mcol], bs8 = BS[mcol+8]; \
        _Pragma("unroll") for (int j = 0; j < 8; j++){ \
            const int nhw = n0 + j*8 + 2*tig; \
            float v0 = acc[j][0]+bs0, v1 = acc[j][1]+bs0; \
            float v2 = acc[j][2]+bs8, v3 = acc[j][3]+bs8; \
            if (Y < 2){ \
                v0 = v0>0.f ? v0+1.f : __expf(v0); v1 = v1>0.f ? v1+1.f : __expf(v1); \
                v2 = v2>0.f ? v2+1.f : __expf(v2); v3 = v3>0.f ? v3+1.f : __expf(v3); \
            } else { v0*=(1.f/T_); v1*=(1.f/T_); v2*=(1.f/T_); v3*=(1.f/T_); } \
            OUTP[(size_t)(r0+nhw  )*C_ + mcol  ] = v0; \
            OUTP[(size_t)(r0+nhw+1)*C_ + mcol  ] = v1; \
            OUTP[(size_t)(r0+nhw  )*C_ + mcol+8] = v2; \
            OUTP[(size_t)(r0+nhw+1)*C_ + mcol+8] = v3; \
        } }

    // ---- Q ----
    ZACC();
    mma_blkW(acc, sWa, sX, 0,12,0,  m0,n0,gid,tig);
    __syncthreads(); fill_w16(sWau, Wk, C_, 0, 96, 0, tid); CPCOMMIT();   // G3
    CPWAIT(1); __syncthreads();                             // G2 done
    mma_blkW(acc, sWb, sX, 12,24,12, m0,n0,gid,tig);
    EPI(g_q, bq, 0);
    __syncthreads(); fill_w16(sWbu, Wk, C_, 96, 96, 0, tid); CPCOMMIT();  // G4
    CPWAIT(1); __syncthreads();                             // G3 done
    // ---- K ----
    ZACC();
    mma_blkW(acc, sWa, sX, 0,12,0,  m0,n0,gid,tig);
    __syncthreads(); fill_w16(sWau, Wv, C_, 0, 96, 0, tid); CPCOMMIT();   // G5
    CPWAIT(1); __syncthreads();                             // G4 done
    mma_blkW(acc, sWb, sX, 12,24,12, m0,n0,gid,tig);
    EPI(g_k, bk, 1);
    __syncthreads(); fill_w16(sWbu, Wv, C_, 96, 32, 0, tid); CPCOMMIT();  // G6
    CPWAIT(1); __syncthreads();                             // G5 done
    // ---- V ----
    ZACC();
    mma_blkW(acc, sWa, sX, 0,12,0,  m0,n0,gid,tig);
    CPWAIT(0); __syncthreads();                             // G6 done
    mma_blkW(acc, sWb, sX, 12,16,12, m0,n0,gid,tig);
    EPI(g_v, bv, 2);
    #undef ZACC
    #undef EPI
}

// ---------------- kernel 2: linear attention, f32x2-packed FMAs ----------
__global__ __launch_bounds__(128) void k_attn()
{
    __shared__ __align__(16) float pool[4224*2 + 256];
    float* pK    = pool;
    float* pV    = pool + 4224;
    float* sKsum = pool + 8448;
    float* sZ    = pool + 8448 + 128;
    const int n = blockIdx.x;
    const int tid = threadIdx.x;

    for (int s = 0; s < 32; s++) {
        pK[s*132 + tid] = g_k[(size_t)(s*N_ + n)*C_ + tid];
        pV[s*132 + tid] = g_v[(size_t)(s*N_ + n)*C_ + tid];
    }
    __syncthreads();

    const int h = tid >> 5, d = tid & 31;
    uint64_t kvp[16];
    #pragma unroll
    for (int i = 0; i < 16; i++) kvp[i] = 0ull;
    float ks = 0.f;
    for (int s = 0; s < 32; s++) {
        float kd = pK[s*132 + h*32 + d];
        ks += kd;
        uint64_t kdp; PACK2(kdp, kd, kd);
        const ulonglong2* vrow2 = (const ulonglong2*)&pV[s*132 + h*32];
        #pragma unroll
        for (int q = 0; q < 8; q++) {
            ulonglong2 vp = vrow2[q];
            FMA2(kvp[2*q  ], kdp, vp.x);
            FMA2(kvp[2*q+1], kdp, vp.y);
        }
    }
    __syncthreads();
    #pragma unroll
    for (int i = 0; i < 16; i++){
        float lo, hi; UNPACK2(lo, hi, kvp[i]);
        pV[h*1056 + d*33 + 2*i    ] = lo;
        pV[h*1056 + d*33 + 2*i + 1] = hi;
    }
    sKsum[tid] = ks;
    for (int s = 0; s < 32; s++)
        pK[s*132 + tid] = g_q[(size_t)(s*N_ + n)*C_ + tid];
    __syncthreads();
    {
        int tz = tid >> 2, hz = tid & 3;
        float z = 0.f;
        #pragma unroll
        for (int dd = 0; dd < 32; dd++)
            z += pK[tz*132 + hz*32 + dd] * sKsum[hz*32 + dd];
        sZ[tz*4 + hz] = (float)T_ / (z + 1e-6f);
    }
    __syncthreads();
    {
        const float* kvb = &pV[h*1056];
        uint64_t kvc[16];
        #pragma unroll
        for (int i = 0; i < 16; i++){
            float lo = kvb[(2*i  )*33 + d];
            float hi = kvb[(2*i+1)*33 + d];
            PACK2(kvc[i], lo, hi);
        }
        for (int tt = 0; tt < 32; tt++) {
            const uint64_t* qrow2 = (const uint64_t*)&pK[tt*132 + h*32];
            uint64_t accp = 0ull;
            #pragma unroll
            for (int i = 0; i < 16; i++)
                FMA2(accp, qrow2[i], kvc[i]);
            float alo, ahi; UNPACK2(alo, ahi, accp);
            g_at[(size_t)(tt*N_ + n)*C_ + tid] = (alo + ahi) * sZ[tt*4 + h];
        }
    }
}

// ---------------- kernel 3: FFN, all-native k-major, fast gelu -----------
// 512 thr, 16 warps (8 wm over out/ffn cols x 2 wn over rows), 128-row tile.
__global__ __launch_bounds__(512) void k_ffn_tc(
    const float* __restrict__ x,
    const float* __restrict__ l1g, const float* __restrict__ l1b,
    const float* __restrict__ l2g, const float* __restrict__ l2b,
    const float* __restrict__ W1,  const float* __restrict__ b1f,
    const float* __restrict__ W2,  const float* __restrict__ b2f,
    float* __restrict__ out)
{
    extern __shared__ float sm[];
    float* sOH = sm;
    float* sU  = sm + 17408;
    float* sWa = sm + 34816;
    float* sWb = sm + 43520;
    float* sM2 = sm + 52224;
    float* sR2 = sm + 52352;
    const uint32_t sWau = (uint32_t)__cvta_generic_to_shared(sWa);
    const uint32_t sWbu = (uint32_t)__cvta_generic_to_shared(sWb);

    const int tid = threadIdx.x;
    const int lane = tid & 31, wid = tid >> 5;
    const int wm = wid >> 1, wn = wid & 1;
    const int gid = lane >> 2, tig = lane & 3;
    const int m0 = wm*16, n0 = wn*64;

    const int r0 = blockIdx.x * 128;
    const int t  = r0 / N_,  nn0 = r0 % N_;
    const int b  = nn0 / HW_, hw0 = nn0 % HW_;

    // pre-issue W1(jc=0) halves so they land during the prologue
    fill_w16(sWau, W1, F_, 0,  64, 0, tid); CPCOMMIT();   // G0
    fill_w16(sWbu, W1, F_, 64, 64, 0, tid); CPCOMMIT();   // G1

    // ---- prologue: sOH[row][c] = attn + ln1(x) ----
    {
        const int cc = (tid & 31) * 4;
        const int rb = tid >> 5;               // 0..15
        for (int j = 0; j < 8; j++) {
            int row = rb + 16*j;
            float4 a = *(const float4*)&g_at[(size_t)(r0+row)*C_ + cc];
            *(float4*)&sOH[row*KNP + cc] = a;
        }
    }
    __syncthreads();
    {
        const int rl = tid & 127, cq = tid >> 7;
        const float mu = g_mu[r0+rl], rs = g_rs[r0+rl];
        const float* xb = x + (size_t)(b*T_+t)*C_*HW_ + hw0 + rl;
        for (int c = cq; c < C_; c += 4)
            sOH[rl*KNP + c] += (xb[(size_t)c*HW_] - mu)*rs*l1g[c] + l1b[c];
    }
    __syncthreads();
    if (tid < 128) {   // ln2 stats, rotated (conflict-free)
        float s = 0.f, s2 = 0.f;
        for (int i = 0; i < 128; i++){
            int c = (i + tid) & 127;
            float v = sOH[tid*KNP + c]; s += v; s2 += v*v;
        }
        float mu = s*(1.f/C_);
        sM2[tid] = mu;
        sR2[tid] = rsqrtf(s2*(1.f/C_) - mu*mu + 1e-5f);
    }
    __syncthreads();
    {   // sU[c][row] = tf32(ln2(O)) — transposed, rotated (conflict-free)
        const int rl = tid & 127, q = tid >> 7;
        const float mu = sM2[rl], rs = sR2[rl];
        for (int i = 0; i < 32; i++){
            int c = q*32 + ((i + rl) & 31);
            float v = (sOH[rl*KNP + c] - mu)*rs*l2g[c] + l2b[c];
            sU[c*KNP + rl] = rna(v);
        }
    }
    // acc2 = O + b2 in D-fragment layout (m=outcol, n=row)
    float acc2[8][4];
    {
        const int mcol = m0 + gid;
        const float bs0 = b2f[mcol], bs8 = b2f[mcol+8];
        #pragma unroll
        for (int j = 0; j < 8; j++){
            const int nhw = n0 + j*8 + 2*tig;
            acc2[j][0] = sOH[(nhw  )*KNP + mcol  ] + bs0;
            acc2[j][1] = sOH[(nhw+1)*KNP + mcol  ] + bs0;
            acc2[j][2] = sOH[(nhw  )*KNP + mcol+8] + bs8;
            acc2[j][3] = sOH[(nhw+1)*KNP + mcol+8] + bs8;
        }
    }
    __syncthreads();   // sU ready; acc2-init reads of sOH done

    float acc1[8][4];
    for (int jc = 0; jc < 4; jc++) {
        CPWAIT(1); __syncthreads();            // W1 lo ready
        {
            const float bs0 = b1f[jc*128 + m0 + gid];
            const float bs8 = b1f[jc*128 + m0 + gid + 8];
            #pragma unroll
            for (int j = 0; j < 8; j++){
                acc1[j][0] = bs0; acc1[j][1] = bs0;
                acc1[j][2] = bs8; acc1[j][3] = bs8;
            }
        }
        mma_blkW(acc1, sWa, sU, 0,8,0,  m0,n0,gid,tig);
        __syncthreads(); fill_w16(sWau, W2, C_, jc*128,     64, 0, tid); CPCOMMIT();
        CPWAIT(1); __syncthreads();            // W1 hi ready
        mma_blkW(acc1, sWb, sU, 8,16,8, m0,n0,gid,tig);
        // gelu (fast tanh) -> sOH as H[ffncol][row]
        {
            const int mloc = m0 + gid;
            #pragma unroll
            for (int j = 0; j < 8; j++){
                const int nhw = n0 + j*8 + 2*tig;
                float g0 = rna(gelu_fast(acc1[j][0]));
                float g1 = rna(gelu_fast(acc1[j][1]));
                float g2 = rna(gelu_fast(acc1[j][2]));
                float g3 = rna(gelu_fast(acc1[j][3]));
                *(float2*)&sOH[(mloc  )*KNP + nhw] = make_float2(g0, g1);
                *(float2*)&sOH[(mloc+8)*KNP + nhw] = make_float2(g2, g3);
            }
        }
        __syncthreads(); fill_w16(sWbu, W2, C_, jc*128+64,  64, 0, tid); CPCOMMIT();
        CPWAIT(1); __syncthreads();            // W2 lo ready
        mma_blkW(acc2, sWa, sOH, 0,8,0,  m0,n0,gid,tig);
        __syncthreads();
        if (jc < 3){ fill_w16(sWau, W1, F_, 0,  64, (jc+1)*128, tid); CPCOMMIT(); }
        if (jc < 3){ CPWAIT(1); } else { CPWAIT(0); }
        __syncthreads();                       // W2 hi ready
        mma_blkW(acc2, sWb, sOH, 8,16,8, m0,n0,gid,tig);
        __syncthreads();
        if (jc < 3){ fill_w16(sWbu, W1, F_, 64, 64, (jc+1)*128, tid); CPCOMMIT(); }
    }

    // ---- epilogue: transposed writeback, consecutive-hw float2 ----
    {
        float* obase = out + (size_t)(b*T_+t)*C_*HW_ + hw0;
        const int mcol = m0 + gid;
        #pragma unroll
        for (int j = 0; j < 8; j++){
            const int nhw = n0 + j*8 + 2*tig;
            *(float2*)&obase[(size_t)(mcol  )*HW_ + nhw] = make_float2(acc2[j][0], acc2[j][1]);
            *(float2*)&obase[(size_t)(mcol+8)*HW_ + nhw] = make_float2(acc2[j][2], acc2[j][3]);
        }
    }
}

// ---------------- launch --------------------------------------------------
extern "C" void kernel_launch(void* const* d_in, const int* in_sizes, int n_in,
                              void* d_out, int out_size)
{
    (void)in_sizes; (void)n_in; (void)out_size;
    const float* x   = (const float*)d_in[0];
    const float* gd  = (const float*)d_in[1];
    const float* Wq  = (const float*)d_in[2];
    const float* bq  = (const float*)d_in[3];
    const float* Wk  = (const float*)d_in[4];
    const float* bk  = (const float*)d_in[5];
    const float* Wv  = (const float*)d_in[6];
    const float* bv  = (const float*)d_in[7];
    const float* l1g = (const float*)d_in[8];
    const float* l1b = (const float*)d_in[9];
    const float* l2g = (const float*)d_in[10];
    const float* l2b = (const float*)d_in[11];
    const float* W1  = (const float*)d_in[12];
    const float* b1  = (const float*)d_in[13];
    const float* W2  = (const float*)d_in[14];
    const float* b2  = (const float*)d_in[15];
    float* out = (float*)d_out;

    const int smemQkv = (192*KNP + 2*96*KNP) * 4;         // 208,896 B
    const int smemFfn = (2*128*KNP + 2*64*KNP + 256) * 4; // 209,920 B
    cudaFuncSetAttribute(k_qkv_tc, cudaFuncAttributeMaxDynamicSharedMemorySize, smemQkv);
    cudaFuncSetAttribute(k_ffn_tc, cudaFuncAttributeMaxDynamicSharedMemorySize, smemFfn);

    k_qkv_tc<<<M_/128, 512, smemQkv>>>(x, gd, Wq, bq, Wk, bk, Wv, bv);
    k_attn  <<<N_, 128>>>();
    k_ffn_tc<<<M_/128, 512, smemFfn>>>(x, l1g, l1b, l2g, l2b, W1, b1, W2, b2, out);
}